// round 15
// baseline (speedup 1.0000x reference)
#include <cuda_runtime.h>
#include <cuda_fp16.h>

// SoftNCutsLoss: B=4, K=8, 32^3, radius 4 -> 251 nonzero offsets per voxel.
// Tile 4x4x32; 1024 threads: thread = (voxel tid&511, offset-half tid>>9).
// OFFSET-SPLIT: half 0 does rows [0,18) (126 offsets), half 1 rows [18,45)
// (125 offsets) - each offset computed ONCE; partials merge in the epilogue
// reduction (A and sumw are additive). 2 CTAs/SM -> 64 warps/SM, 13.8/SMSP.
//   sQ[v]  = uint4, 8 x fp16 preds (LDS.128)
//   sIp[v] = half2 {Is[v], Is[v+1]}, PRE-SCALED by sqrt(log2e)/10
// dz pairs: arg = fma(d, -d, C); ex2.approx.f16x2 (one asm op). Native __half2
// elsewhere (HFMA2 modifier folds, R14-verified). Compile-time row structure.
// Chunked fp32 flushes (<=42 adds). Last-CTA fused finalize.

#define EPSV 2.2204460492503131e-16f
#define TPX 10
#define TPY 10
#define TPZ 38
#define NPAD (TPX * TPY * TPZ)      // 3800
#define SMEM_BYTES (NPAD * 16 + NPAD * 4)

typedef unsigned uu;

__device__ float gPart[256 * 16];   // per-CTA partials [cta][0..7]=A, [8..15]=V
__device__ unsigned gCount;         // zero-init; last CTA resets

// ---------- compile-time fp16 constant tables ----------
constexpr unsigned short f2h(float x) {
    unsigned u = __builtin_bit_cast(unsigned, x);
    unsigned s = (u >> 16) & 0x8000u;
    int e = (int)((u >> 23) & 0xFF) - 127 + 15;
    unsigned m = u & 0x7FFFFFu;
    if (x == 0.0f) return (unsigned short)s;
    if (e >= 31) return (unsigned short)(s | 0x7C00u);      // inf
    if (e <= 0) return (unsigned short)s;                    // flush tiny
    unsigned h = s | ((unsigned)e << 10) | (m >> 13);
    unsigned rem = m & 0x1FFFu;
    if (rem > 0x1000u || (rem == 0x1000u && (h & 1u))) h++;
    return (unsigned short)h;
}
constexpr unsigned h2c(float lo, float hi) {
    return (unsigned)f2h(lo) | ((unsigned)f2h(hi) << 16);
}

struct RT {
    int voff[45];
    int m[45];
    unsigned cp[45][4];   // packed fp16 exponent constant per dz-pair
};
constexpr RT mkrt() {
    RT t{};
    const float K3 = -0.09016844005556021f;   // -log2(e)/16
    int idx = 0;
    for (int want = 3; want >= 1; want--)
        for (int dx = -3; dx <= 3; dx++)
            for (int dy = -3; dy <= 3; dy++) {
                int r2 = 16 - dx * dx - dy * dy;
                int m = 0;
                if (r2 >= 10) m = 3;
                else if (r2 >= 5) m = 2;
                else if (r2 >= 2) m = 1;
                else continue;
                if (m != want) continue;
                t.voff[idx] = dx * (TPY * TPZ) + dy * TPZ;
                t.m[idx] = m;
                int d2r = dx * dx + dy * dy;
                int jp = 0;
                for (int dzE = -m; dzE <= m; dzE += 2) {
                    float clo = (float)(d2r + dzE * dzE) * K3;
                    float chi = (float)(d2r + (dzE + 1) * (dzE + 1)) * K3;
                    bool dum = (dzE + 1 > m);
                    t.cp[idx][jp++] = dum ? ((unsigned)f2h(clo) | 0xFC000000u)  // hi=-inf
                                          : h2c(clo, chi);
                }
                idx++;
            }
    return t;
}
constexpr RT RTc = mkrt();   // compile-time only; accessed via template indices

// unsigned bits -> __half2 (folds to immediate when u is a constant)
__device__ __forceinline__ __half2 hbits(unsigned u) {
    __half2_raw r;
    r.x = (unsigned short)(u & 0xFFFFu);
    r.y = (unsigned short)(u >> 16);
    return __half2(r);
}
__device__ __forceinline__ __half2 u2h2(unsigned u) {
    return *reinterpret_cast<const __half2*>(&u);
}
// the ONE asm op: fp16x2 approx exp2 (h2exp2 lowers via fp32 - R13 regression)
__device__ __forceinline__ __half2 ex2_h2(__half2 x) {
    __half2 r;
    asm("ex2.approx.f16x2 %0, %1;"
        : "=r"(*reinterpret_cast<unsigned*>(&r))
        : "r"(*reinterpret_cast<const unsigned*>(&x)));
    return r;
}

// ---------- accumulator state ----------
struct Acc {
    __half2 a0, a1, a2, a3, hsw;
    float f[8];
    float fsw;
};

__device__ __forceinline__ void flush_all(Acc& A) {
    float2 t;
    t = __half22float2(A.a0);  A.f[0] += t.x; A.f[1] += t.y; A.a0 = __half2(__half2_raw{0,0});
    t = __half22float2(A.a1);  A.f[2] += t.x; A.f[3] += t.y; A.a1 = __half2(__half2_raw{0,0});
    t = __half22float2(A.a2);  A.f[4] += t.x; A.f[5] += t.y; A.a2 = __half2(__half2_raw{0,0});
    t = __half22float2(A.a3);  A.f[6] += t.x; A.f[7] += t.y; A.a3 = __half2(__half2_raw{0,0});
    t = __half22float2(A.hsw); A.fsw  += t.x + t.y;          A.hsw = __half2(__half2_raw{0,0});
}

// ---------- fully compile-time row/pair expansion ----------
template<int I, int JP>
__device__ __forceinline__ void do_pairs(Acc& A, __half2 I2, const uint4* sQ,
                                         const __half2* sIp, int v0) {
    constexpr int M = RTc.m[I];
    if constexpr (JP <= M) {
        constexpr int dzE  = -M + 2 * JP;
        constexpr int OFF  = RTc.voff[I] + dzE;     // compile-time offset
        constexpr uu  CP   = RTc.cp[I][JP];         // immediate constant
        constexpr bool FULL = (JP < M);             // last pair has dummy hi

        const int vp = v0 + OFF;
        const __half2 ip  = sIp[vp];                // {Is[vp], Is[vp+1]}
        const __half2 d   = __hsub2(I2, ip);
        const __half2 arg = __hfma2(d, __hneg2(d), hbits(CP));   // C - d^2
        const __half2 a2  = ex2_h2(arg);            // lo=a(dzE), hi=a(dzE+1)|0
        A.hsw = __hadd2(A.hsw, a2);
        const uint4 ql = sQ[vp];
        const __half2 aE = __low2half2(a2);         // -> HFMA2 .H0_H0 fold
        A.a0 = __hfma2(aE, u2h2(ql.x), A.a0);
        A.a1 = __hfma2(aE, u2h2(ql.y), A.a1);
        A.a2 = __hfma2(aE, u2h2(ql.z), A.a2);
        A.a3 = __hfma2(aE, u2h2(ql.w), A.a3);
        if constexpr (FULL) {
            const uint4 qh = sQ[vp + 1];
            const __half2 aO = __high2half2(a2);    // -> HFMA2 .H1_H1 fold
            A.a0 = __hfma2(aO, u2h2(qh.x), A.a0);
            A.a1 = __hfma2(aO, u2h2(qh.y), A.a1);
            A.a2 = __hfma2(aO, u2h2(qh.z), A.a2);
            A.a3 = __hfma2(aO, u2h2(qh.w), A.a3);
        }
        do_pairs<I, JP + 1>(A, I2, sQ, sIp, v0);
    }
}

template<int I, int IEND>
__device__ __forceinline__ void do_rows(Acc& A, __half2 I2, const uint4* sQ,
                                        const __half2* sIp, int v0) {
    if constexpr (I < IEND) {
        do_pairs<I, 0>(A, I2, sQ, sIp, v0);
        // flush points chosen so every chunk is <= 42 fp16 adds
        if constexpr (I == 5 || I == 11 || I == 24 || I == 31 || I == 38)
            flush_all(A);
        do_rows<I + 1, IEND>(A, I2, sQ, sIp, v0);
    }
}

__global__ __launch_bounds__(1024, 2)
void soft_ncuts_main(const float* __restrict__ batch, const float* __restrict__ preds,
                     float* __restrict__ out) {
    extern __shared__ char smem_raw[];
    uint4*          sQ   = (uint4*)smem_raw;                   // 16 B/voxel fp16 preds
    __half2*        sIp  = (__half2*)(smem_raw + NPAD * 16);   // {Is[v], Is[v+1]}
    unsigned short* sIph = (unsigned short*)sIp;

    const int tid  = threadIdx.x;          // 0..1023
    const int vtid = tid & 511;            // voxel in tile
    const int hh   = tid >> 9;             // offset-half: 0 -> rows [0,18), 1 -> [18,45)
    const int b    = blockIdx.y;
    const int bx   = blockIdx.x;           // 0..63
    const int ox   = (bx >> 3) * 4;
    const int oy   = (bx & 7) * 4;

    const float* batchb = batch + b * 32768;
    const float* predsb = preds + (b * 8) * 32768;

    const float SQ = 0.12011224087864498f;   // sqrt(log2(e))/10

    // zero the single never-written hi half (entry NPAD-1)
    if (tid == 0) sIph[2 * (NPAD - 1) + 1] = 0;

    // ---- stage padded 10x10x38 tile; out-of-volume = EPS ----
    for (int v = tid; v < NPAD; v += 1024) {
        int px = v / (TPY * TPZ);
        int r  = v - px * (TPY * TPZ);
        int py = r / TPZ;
        int pz = r - py * TPZ;
        int gx = ox + px - 3, gy = oy + py - 3, gz = pz - 3;
        bool inb = ((unsigned)gx < 32u) && ((unsigned)gy < 32u) && ((unsigned)gz < 32u);
        int g = gx * 1024 + gy * 32 + gz;
        float I = inb ? batchb[g] : EPSV;
        float p[8];
#pragma unroll
        for (int k = 0; k < 8; k++) p[k] = inb ? predsb[k * 32768 + g] : EPSV;
        __half2 h01 = __floats2half2_rn(p[0], p[1]);
        __half2 h23 = __floats2half2_rn(p[2], p[3]);
        __half2 h45 = __floats2half2_rn(p[4], p[5]);
        __half2 h67 = __floats2half2_rn(p[6], p[7]);
        uint4 Q;
        Q.x = *reinterpret_cast<unsigned*>(&h01);
        Q.y = *reinterpret_cast<unsigned*>(&h23);
        Q.z = *reinterpret_cast<unsigned*>(&h45);
        Q.w = *reinterpret_cast<unsigned*>(&h67);
        sQ[v] = Q;
        unsigned short Ih = __half_as_ushort(__float2half_rn(I * SQ));
        sIph[2 * v] = Ih;                    // entry v lo = Is[v]
        if (v > 0) sIph[2 * v - 1] = Ih;     // entry v-1 hi = Is[v]
    }
    __syncthreads();

    // voxel mapping: lane = z, warp-of-voxel -> (wx, wy)
    const int lz = vtid & 31;
    const int wy = (vtid >> 5) & 3;
    const int wx = vtid >> 7;
    const int v0 = (wx + 3) * (TPY * TPZ) + (wy + 3) * TPZ + (lz + 3);
    const __half2 I2 = __low2half2(sIp[v0]);   // own scaled intensity, both halves

    Acc A;
    A.a0 = A.a1 = A.a2 = A.a3 = A.hsw = __half2(__half2_raw{0, 0});
#pragma unroll
    for (int k = 0; k < 8; k++) A.f[k] = 0.f;
    A.fsw = 0.f;

    if (hh == 0) {
        do_rows<0, 18>(A, I2, sQ, sIp, v0);    // 126 offsets
    } else {
        do_rows<18, 45>(A, I2, sQ, sIp, v0);   // 125 offsets
    }
    flush_all(A);

    const float sumw = A.fsw;

    // ---- epilogue: own preds exact fp32 from global; halves merge via sRed ----
    const int g0 = (ox + wx) * 1024 + (oy + wy) * 32 + lz;
    float c[16];
#pragma unroll
    for (int k = 0; k < 8; k++) {
        float q = predsb[k * 32768 + g0];
        c[k]     = A.f[k] * q;
        c[8 + k] = sumw * q;
    }

    __shared__ float sRed[16];
    if (tid < 16) sRed[tid] = 0.f;
    __syncthreads();
#pragma unroll
    for (int j = 0; j < 16; j++) {
        float val = c[j];
#pragma unroll
        for (int o = 16; o; o >>= 1) val += __shfl_xor_sync(0xffffffffu, val, o);
        if ((tid & 31) == 0) atomicAdd(&sRed[j], val);
    }
    __syncthreads();
    if (tid < 16) gPart[(b * 64 + bx) * 16 + tid] = sRed[tid];
    __syncthreads();

    // ---- fused finalize: last CTA reduces all partials ----
    __shared__ unsigned sLast;
    if (tid == 0) {
        __threadfence();
        unsigned t = atomicAdd(&gCount, 1u);
        sLast = (t == 255u) ? 1u : 0u;
    }
    __syncthreads();
    if (sLast) {
        __shared__ float sAV[64];
        if (tid < 64) sAV[tid] = 0.f;
        __syncthreads();
        if (tid < 256) {
            const int bb = tid >> 6;            // 4
            const int jj = (tid >> 2) & 15;     // 16
            const int ch = tid & 3;             // 4 chunks of 16 CTAs
            float s = 0.f;
#pragma unroll
            for (int t2 = 0; t2 < 16; t2++)
                s += __ldcg(&gPart[(bb * 64 + ch * 16 + t2) * 16 + jj]);
            atomicAdd(&sAV[bb * 16 + jj], s);
        }
        __syncthreads();
        if (tid < 4) {
            float s2 = 0.f;
#pragma unroll
            for (int k = 0; k < 8; k++)
                s2 += sAV[tid * 16 + k] / sAV[tid * 16 + 8 + k];
            out[tid] = 8.f - s2;
        }
        if (tid == 0) gCount = 0u;
    }
}

extern "C" void kernel_launch(void* const* d_in, const int* in_sizes, int n_in,
                              void* d_out, int out_size) {
    const float* batch = (const float*)d_in[0];
    const float* preds = (const float*)d_in[1];
    float* out = (float*)d_out;

    cudaFuncSetAttribute(soft_ncuts_main, cudaFuncAttributeMaxDynamicSharedMemorySize,
                         SMEM_BYTES);

    dim3 grid(64, 4);
    soft_ncuts_main<<<grid, 1024, SMEM_BYTES>>>(batch, preds, out);
}

// round 16
// speedup vs baseline: 1.4069x; 1.4069x over previous
#include <cuda_runtime.h>
#include <cuda_fp16.h>

// SoftNCutsLoss via affinity SYMMETRY: a(p,q)=a(q,p), and outputs are quadratic
// forms, so only the 125 lexicographically-POSITIVE offsets (74 dz-pairs) are
// iterated — half the smem traffic / exp / MACs of the 251-offset version.
//   assocA[k] = sum_p pred*(2*sq_k + pred)            (sq_k = sum_pos a*pred(q))
//   assocV[k] = sum_p [pred*(1 + sumwh + g*Wmiss) + sq_k]
//     g = exp(-(Ip-eps)^2/100); Wmiss = sum_pos w(off)*[p-off not in volume]
//     (covers reference's backward-into-padding terms; pad pred=EPS makes all
//      other cross terms O(1e-16)).
// Tile 4x4x32, 512 thr, 1 voxel/thread, warp = 32 z, 2 CTAs/SM.
//   sQ[v]=16B fp16 preds; sIp[v]=half2{Is[v],Is[v+1]} (prescaled sqrt(log2e)/10);
//   sVo[v]=half2{vout[v],vout[v+1]} (1.0 if padding).
// ex2.approx.f16x2 is the one asm op; native __half2 elsewhere (modifier folds).

#define EPSV 2.2204460492503131e-16f
#define TPX 10
#define TPY 10
#define TPZ 38
#define NPAD (TPX * TPY * TPZ)      // 3800
#define SMEM_BYTES (NPAD * 24)

typedef unsigned uu;

__device__ float gPart[256 * 16];
__device__ unsigned gCount;

// ---------- compile-time helpers ----------
constexpr unsigned short f2h(float x) {
    unsigned u = __builtin_bit_cast(unsigned, x);
    unsigned s = (u >> 16) & 0x8000u;
    int e = (int)((u >> 23) & 0xFF) - 127 + 15;
    unsigned m = u & 0x7FFFFFu;
    if (x == 0.0f) return (unsigned short)s;
    if (e >= 31) return (unsigned short)(s | 0x7C00u);
    if (e <= 0) return (unsigned short)s;
    unsigned h = s | ((unsigned)e << 10) | (m >> 13);
    unsigned rem = m & 0x1FFFu;
    if (rem > 0x1000u || (rem == 0x1000u && (h & 1u))) h++;
    return (unsigned short)h;
}
constexpr unsigned h2c(float lo, float hi) {
    return (unsigned)f2h(lo) | ((unsigned)f2h(hi) << 16);
}
constexpr double cexp(double x) {   // Taylor, |x|<=1, 18 terms
    double s = 1.0;
    for (int i = 18; i >= 1; i--) s = 1.0 + x * s / i;
    return s;
}
constexpr float wspat(int d2) { return (float)cexp(-(double)d2 / 16.0); }

struct RT2 {
    int voff[23];
    int dzs[23];
    int np[23];
    unsigned cp[23][4];   // forward exponent const per pair (hi=-inf if dummy)
    unsigned wr[23][4];   // reverse w const per pair (lo<->off_hi, hi<->off_lo)
};
constexpr RT2 mkrt2() {
    RT2 t{};
    const float K3 = -0.09016844005556021f;   // -log2(e)/16
    int idx = 0;
    for (int dx = 0; dx <= 3; dx++)
        for (int dy = -3; dy <= 3; dy++) {
            if (dx == 0 && dy < 0) continue;
            int r2 = 16 - dx * dx - dy * dy;
            int m = 0;
            if (r2 >= 10) m = 3;
            else if (r2 >= 5) m = 2;
            else if (r2 >= 2) m = 1;
            else continue;
            int dzs = 0, cnt = 0;
            if (dx == 0 && dy == 0) { dzs = 1; cnt = 3; }   // self excluded
            else { dzs = -m; cnt = 2 * m + 1; }
            int np = (cnt + 1) / 2;
            int d2r = dx * dx + dy * dy;
            t.voff[idx] = dx * (TPY * TPZ) + dy * TPZ;
            t.dzs[idx] = dzs;
            t.np[idx] = np;
            int dzend = dzs + cnt - 1;
            for (int jp = 0; jp < np; jp++) {
                int dzE = dzs + 2 * jp;
                bool full = (dzE + 1 <= dzend);
                float clo = (float)(d2r + dzE * dzE) * K3;
                if (full) {
                    float chi = (float)(d2r + (dzE + 1) * (dzE + 1)) * K3;
                    t.cp[idx][jp] = h2c(clo, chi);
                    t.wr[idx][jp] = h2c(wspat(d2r + (dzE + 1) * (dzE + 1)),
                                        wspat(d2r + dzE * dzE));
                } else {
                    t.cp[idx][jp] = (unsigned)f2h(clo) | 0xFC000000u;  // hi=-inf
                    t.wr[idx][jp] = h2c(wspat(d2r + dzE * dzE), 0.0f);
                }
            }
            idx++;
        }
    return t;
}
constexpr RT2 R2 = mkrt2();   // 23 rows, 74 pairs, 125 offsets

__device__ __forceinline__ __half2 hbits(unsigned u) {
    __half2_raw r;
    r.x = (unsigned short)(u & 0xFFFFu);
    r.y = (unsigned short)(u >> 16);
    return __half2(r);
}
__device__ __forceinline__ __half2 u2h2(unsigned u) {
    return *reinterpret_cast<const __half2*>(&u);
}
__device__ __forceinline__ __half2 ex2_h2(__half2 x) {
    __half2 r;
    asm("ex2.approx.f16x2 %0, %1;"
        : "=r"(*reinterpret_cast<unsigned*>(&r))
        : "r"(*reinterpret_cast<const unsigned*>(&x)));
    return r;
}
__device__ __forceinline__ float ex2f(float x) {
    float r; asm("ex2.approx.f32 %0, %1;" : "=f"(r) : "f"(x)); return r;
}

// ---------- accumulator ----------
struct Acc {
    __half2 a0, a1, a2, a3, hsw;
    float f[8];
    float fsw;
};
__device__ __forceinline__ void flush_all(Acc& A) {
    float2 t;
    t = __half22float2(A.a0);  A.f[0] += t.x; A.f[1] += t.y; A.a0 = __half2(__half2_raw{0,0});
    t = __half22float2(A.a1);  A.f[2] += t.x; A.f[3] += t.y; A.a1 = __half2(__half2_raw{0,0});
    t = __half22float2(A.a2);  A.f[4] += t.x; A.f[5] += t.y; A.a2 = __half2(__half2_raw{0,0});
    t = __half22float2(A.a3);  A.f[6] += t.x; A.f[7] += t.y; A.a3 = __half2(__half2_raw{0,0});
    t = __half22float2(A.hsw); A.fsw  += t.x + t.y;          A.hsw = __half2(__half2_raw{0,0});
}

// ---------- forward pass (positive offsets) ----------
template<int I, int JP>
__device__ __forceinline__ void do_pairsF(Acc& A, __half2 I2, const uint4* sQ,
                                          const __half2* sIp, int v0) {
    constexpr int NP = R2.np[I];
    if constexpr (JP < NP) {
        constexpr int dzE  = R2.dzs[I] + 2 * JP;
        constexpr int OFF  = R2.voff[I] + dzE;
        constexpr uu  CP   = R2.cp[I][JP];
        constexpr bool FULL = (JP < NP - 1);

        const int vp = v0 + OFF;
        const __half2 ip  = sIp[vp];
        const __half2 d   = __hsub2(I2, ip);
        const __half2 arg = __hfma2(d, __hneg2(d), hbits(CP));
        const __half2 a2  = ex2_h2(arg);
        A.hsw = __hadd2(A.hsw, a2);
        const uint4 ql = sQ[vp];
        const __half2 aE = __low2half2(a2);
        A.a0 = __hfma2(aE, u2h2(ql.x), A.a0);
        A.a1 = __hfma2(aE, u2h2(ql.y), A.a1);
        A.a2 = __hfma2(aE, u2h2(ql.z), A.a2);
        A.a3 = __hfma2(aE, u2h2(ql.w), A.a3);
        if constexpr (FULL) {
            const uint4 qh = sQ[vp + 1];
            const __half2 aO = __high2half2(a2);
            A.a0 = __hfma2(aO, u2h2(qh.x), A.a0);
            A.a1 = __hfma2(aO, u2h2(qh.y), A.a1);
            A.a2 = __hfma2(aO, u2h2(qh.z), A.a2);
            A.a3 = __hfma2(aO, u2h2(qh.w), A.a3);
        }
        do_pairsF<I, JP + 1>(A, I2, sQ, sIp, v0);
    }
}

template<int I>
__device__ __forceinline__ void do_rowsF(Acc& A, __half2 I2, const uint4* sQ,
                                         const __half2* sIp, int v0) {
    if constexpr (I < 23) {
        do_pairsF<I, 0>(A, I2, sQ, sIp, v0);
        if constexpr (I == 7 || I == 12 || I == 17) flush_all(A);
        do_rowsF<I + 1>(A, I2, sQ, sIp, v0);
    }
}

// ---------- reverse validity pass: Wmiss = sum w * vout(p - off) ----------
template<int I, int JP>
__device__ __forceinline__ void do_pairsR(__half2& wm, const __half2* sVo, int v0) {
    constexpr int NP = R2.np[I];
    if constexpr (JP < NP) {
        constexpr int dzE  = R2.dzs[I] + 2 * JP;
        constexpr bool FULL = (JP < NP - 1);
        constexpr int OFFR = R2.voff[I] + dzE + (FULL ? 1 : 0);
        constexpr uu  WR   = R2.wr[I][JP];
        wm = __hfma2(hbits(WR), sVo[v0 - OFFR], wm);
        do_pairsR<I, JP + 1>(wm, sVo, v0);
    }
}

template<int I>
__device__ __forceinline__ void do_rowsR(__half2& wm, float& wmf,
                                         const __half2* sVo, int v0) {
    if constexpr (I < 23) {
        do_pairsR<I, 0>(wm, sVo, v0);
        if constexpr (I == 11) {
            float2 t = __half22float2(wm);
            wmf += t.x + t.y;
            wm = __half2(__half2_raw{0, 0});
        }
        do_rowsR<I + 1>(wm, wmf, sVo, v0);
    }
}

__global__ __launch_bounds__(512, 2)
void soft_ncuts_main(const float* __restrict__ batch, const float* __restrict__ preds,
                     float* __restrict__ out) {
    extern __shared__ char smem_raw[];
    uint4*          sQ   = (uint4*)smem_raw;
    __half2*        sIp  = (__half2*)(smem_raw + NPAD * 16);
    __half2*        sVo  = (__half2*)(smem_raw + NPAD * 20);
    unsigned short* sIph = (unsigned short*)sIp;
    unsigned short* sVoh = (unsigned short*)sVo;

    const int tid = threadIdx.x;
    const int b   = blockIdx.y;
    const int bx  = blockIdx.x;
    const int ox  = (bx >> 3) * 4;
    const int oy  = (bx & 7) * 4;

    const float* batchb = batch + b * 32768;
    const float* predsb = preds + (b * 8) * 32768;

    const float SQ = 0.12011224087864498f;   // sqrt(log2(e))/10

    if (tid == 0) {
        sIph[2 * (NPAD - 1) + 1] = 0;
        sVoh[2 * (NPAD - 1) + 1] = 0;
    }

    // ---- stage padded tile; out-of-volume = EPS (preds), vout=1 ----
    for (int v = tid; v < NPAD; v += 512) {
        int px = v / (TPY * TPZ);
        int r  = v - px * (TPY * TPZ);
        int py = r / TPZ;
        int pz = r - py * TPZ;
        int gx = ox + px - 3, gy = oy + py - 3, gz = pz - 3;
        bool inb = ((unsigned)gx < 32u) && ((unsigned)gy < 32u) && ((unsigned)gz < 32u);
        int g = gx * 1024 + gy * 32 + gz;
        float I = inb ? batchb[g] : EPSV;
        float p[8];
#pragma unroll
        for (int k = 0; k < 8; k++) p[k] = inb ? predsb[k * 32768 + g] : EPSV;
        __half2 h01 = __floats2half2_rn(p[0], p[1]);
        __half2 h23 = __floats2half2_rn(p[2], p[3]);
        __half2 h45 = __floats2half2_rn(p[4], p[5]);
        __half2 h67 = __floats2half2_rn(p[6], p[7]);
        uint4 Q;
        Q.x = *reinterpret_cast<unsigned*>(&h01);
        Q.y = *reinterpret_cast<unsigned*>(&h23);
        Q.z = *reinterpret_cast<unsigned*>(&h45);
        Q.w = *reinterpret_cast<unsigned*>(&h67);
        sQ[v] = Q;
        unsigned short Ih = __half_as_ushort(__float2half_rn(I * SQ));
        unsigned short Vh = inb ? (unsigned short)0 : (unsigned short)0x3C00;  // 1.0
        sIph[2 * v] = Ih;
        sVoh[2 * v] = Vh;
        if (v > 0) { sIph[2 * v - 1] = Ih; sVoh[2 * v - 1] = Vh; }
    }
    __syncthreads();

    const int lz = tid & 31;
    const int wy = (tid >> 5) & 3;
    const int wx = tid >> 7;
    const int v0 = (wx + 3) * (TPY * TPZ) + (wy + 3) * TPZ + (lz + 3);
    const __half2 I2 = __low2half2(sIp[v0]);

    Acc A;
    A.a0 = A.a1 = A.a2 = A.a3 = A.hsw = __half2(__half2_raw{0, 0});
#pragma unroll
    for (int k = 0; k < 8; k++) A.f[k] = 0.f;
    A.fsw = 0.f;

    do_rowsF<0>(A, I2, sQ, sIp, v0);
    flush_all(A);

    // reverse validity pass
    __half2 wm = __half2(__half2_raw{0, 0});
    float wmf = 0.f;
    do_rowsR<0>(wm, wmf, sVo, v0);
    {
        float2 t = __half22float2(wm);
        wmf += t.x + t.y;
    }

    // g = exp(-(Ip-eps)^2/100) = exp2(-(Is)^2)
    const float Isf = __half2float(__low2half(I2));
    const float gfac = ex2f(-Isf * Isf);
    const float vbase = A.fsw + 1.f + gfac * wmf;

    // ---- epilogue: exact fp32 preds from global ----
    const int g0 = (ox + wx) * 1024 + (oy + wy) * 32 + lz;
    float c[16];
#pragma unroll
    for (int k = 0; k < 8; k++) {
        float q = predsb[k * 32768 + g0];
        c[k]     = (2.f * A.f[k] + q) * q;    // assocA: 2*cross + diag
        c[8 + k] = q * vbase + A.f[k];        // assocV: fwd+diag+miss, + q-side
    }

    __shared__ float sRed[16];
    if (tid < 16) sRed[tid] = 0.f;
    __syncthreads();
#pragma unroll
    for (int j = 0; j < 16; j++) {
        float val = c[j];
#pragma unroll
        for (int o = 16; o; o >>= 1) val += __shfl_xor_sync(0xffffffffu, val, o);
        if ((tid & 31) == 0) atomicAdd(&sRed[j], val);
    }
    __syncthreads();
    if (tid < 16) gPart[(b * 64 + bx) * 16 + tid] = sRed[tid];
    __syncthreads();

    // ---- fused finalize ----
    __shared__ unsigned sLast;
    if (tid == 0) {
        __threadfence();
        unsigned t = atomicAdd(&gCount, 1u);
        sLast = (t == 255u) ? 1u : 0u;
    }
    __syncthreads();
    if (sLast) {
        __shared__ float sAV[64];
        if (tid < 64) sAV[tid] = 0.f;
        __syncthreads();
        if (tid < 256) {
            const int bb = tid >> 6;
            const int jj = (tid >> 2) & 15;
            const int ch = tid & 3;
            float s = 0.f;
#pragma unroll
            for (int t2 = 0; t2 < 16; t2++)
                s += __ldcg(&gPart[(bb * 64 + ch * 16 + t2) * 16 + jj]);
            atomicAdd(&sAV[bb * 16 + jj], s);
        }
        __syncthreads();
        if (tid < 4) {
            float s2 = 0.f;
#pragma unroll
            for (int k = 0; k < 8; k++)
                s2 += sAV[tid * 16 + k] / sAV[tid * 16 + 8 + k];
            out[tid] = 8.f - s2;
        }
        if (tid == 0) gCount = 0u;
    }
}

extern "C" void kernel_launch(void* const* d_in, const int* in_sizes, int n_in,
                              void* d_out, int out_size) {
    const float* batch = (const float*)d_in[0];
    const float* preds = (const float*)d_in[1];
    float* out = (float*)d_out;

    cudaFuncSetAttribute(soft_ncuts_main, cudaFuncAttributeMaxDynamicSharedMemorySize,
                         SMEM_BYTES);

    dim3 grid(64, 4);
    soft_ncuts_main<<<grid, 512, SMEM_BYTES>>>(batch, preds, out);
}

// round 17
// speedup vs baseline: 1.4343x; 1.0195x over previous
#include <cuda_runtime.h>
#include <cuda_fp16.h>

// SoftNCutsLoss via affinity symmetry: only the 125 positive offsets (74 dz
// pairs) iterated. Boundary correction Wmiss(p) = sum_pos w(off)*[p-off not in
// volume] is a pure function of clamped boundary distances -> compile-time
// 1024-entry __constant__ table (replaces R16's reverse smem pass + sVo).
//   assocA[k] = sum_p q*(2*sq_k + q)
//   assocV[k] = sum_p [q*(1 + sumw_fwd + g*Wmiss) + sq_k],  g = exp2(-Is^2)
// Tile 4x4x32, 512 thr, 1 voxel/thread, warp = 32 z, 2 CTAs/SM.
//   sQ[v]=16B fp16 preds; sIp[v]=half2{Is[v],Is[v+1]} (prescaled sqrt(log2e)/10)
// ex2.approx.f16x2 is the one asm op; native __half2 elsewhere (modifier folds).
// Epilogue preds from sQ (fp16) - no global reload. Last-CTA fused finalize.

#define EPSV 2.2204460492503131e-16f
#define TPX 10
#define TPY 10
#define TPZ 38
#define NPAD (TPX * TPY * TPZ)      // 3800
#define SMEM_BYTES (NPAD * 20)

typedef unsigned uu;

__device__ float gPart[256 * 16];
__device__ unsigned gCount;

// ---------- compile-time helpers ----------
constexpr unsigned short f2h(float x) {
    unsigned u = __builtin_bit_cast(unsigned, x);
    unsigned s = (u >> 16) & 0x8000u;
    int e = (int)((u >> 23) & 0xFF) - 127 + 15;
    unsigned m = u & 0x7FFFFFu;
    if (x == 0.0f) return (unsigned short)s;
    if (e >= 31) return (unsigned short)(s | 0x7C00u);
    if (e <= 0) return (unsigned short)s;
    unsigned h = s | ((unsigned)e << 10) | (m >> 13);
    unsigned rem = m & 0x1FFFu;
    if (rem > 0x1000u || (rem == 0x1000u && (h & 1u))) h++;
    return (unsigned short)h;
}
constexpr unsigned h2c(float lo, float hi) {
    return (unsigned)f2h(lo) | ((unsigned)f2h(hi) << 16);
}
constexpr double cexp(double x) {   // Taylor, |x|<=1, 18 terms
    double s = 1.0;
    for (int i = 18; i >= 1; i--) s = 1.0 + x * s / i;
    return s;
}

// ---- positive-offset row table (23 rows, 74 pairs, 125 offsets) ----
struct RT2 {
    int voff[23];
    int dzs[23];
    int np[23];
    unsigned cp[23][4];   // fp16x2 exponent const per dz-pair (hi=-inf if dummy)
};
constexpr RT2 mkrt2() {
    RT2 t{};
    const float K3 = -0.09016844005556021f;   // -log2(e)/16
    int idx = 0;
    for (int dx = 0; dx <= 3; dx++)
        for (int dy = -3; dy <= 3; dy++) {
            if (dx == 0 && dy < 0) continue;
            int r2 = 16 - dx * dx - dy * dy;
            int m = 0;
            if (r2 >= 10) m = 3;
            else if (r2 >= 5) m = 2;
            else if (r2 >= 2) m = 1;
            else continue;
            int dzs = 0, cnt = 0;
            if (dx == 0 && dy == 0) { dzs = 1; cnt = 3; }   // self excluded
            else { dzs = -m; cnt = 2 * m + 1; }
            int np = (cnt + 1) / 2;
            int d2r = dx * dx + dy * dy;
            t.voff[idx] = dx * (TPY * TPZ) + dy * TPZ;
            t.dzs[idx] = dzs;
            t.np[idx] = np;
            int dzend = dzs + cnt - 1;
            for (int jp = 0; jp < np; jp++) {
                int dzE = dzs + 2 * jp;
                bool full = (dzE + 1 <= dzend);
                float clo = (float)(d2r + dzE * dzE) * K3;
                if (full) {
                    float chi = (float)(d2r + (dzE + 1) * (dzE + 1)) * K3;
                    t.cp[idx][jp] = h2c(clo, chi);
                } else {
                    t.cp[idx][jp] = (unsigned)f2h(clo) | 0xFC000000u;  // hi=-inf
                }
            }
            idx++;
        }
    return t;
}
constexpr RT2 R2 = mkrt2();

// ---- Wmiss table: f(min(gx,3), min(gy,3), min(31-gy,3), min(gz,3), min(31-gz,3)) ----
struct WT { float w[1024]; };
constexpr WT mkwt() {
    WT t{};
    double warr[16] = {};
    for (int d2 = 0; d2 < 16; d2++) warr[d2] = cexp(-(double)d2 / 16.0);
    for (int ix = 0; ix < 4; ix++)
    for (int iy0 = 0; iy0 < 4; iy0++)
    for (int iy1 = 0; iy1 < 4; iy1++)
    for (int iz0 = 0; iz0 < 4; iz0++)
    for (int iz1 = 0; iz1 < 4; iz1++) {
        double s = 0.0;
        for (int dx = 0; dx <= 3; dx++)
        for (int dy = -3; dy <= 3; dy++)
        for (int dz = -3; dz <= 3; dz++) {
            if (dx == 0 && (dy < 0 || (dy == 0 && dz <= 0))) continue;  // pos-lex only
            int d2 = dx * dx + dy * dy + dz * dz;
            if (d2 >= 16) continue;
            bool miss = (dx > ix) || (dy > 0 && dy > iy0) || (dy < 0 && -dy > iy1)
                     || (dz > 0 && dz > iz0) || (dz < 0 && -dz > iz1);
            if (miss) s += warr[d2];
        }
        t.w[(((ix * 4 + iy0) * 4 + iy1) * 4 + iz0) * 4 + iz1] = (float)s;
    }
    return t;
}
__constant__ WT WTT = mkwt();

__device__ __forceinline__ __half2 hbits(unsigned u) {
    __half2_raw r;
    r.x = (unsigned short)(u & 0xFFFFu);
    r.y = (unsigned short)(u >> 16);
    return __half2(r);
}
__device__ __forceinline__ __half2 u2h2(unsigned u) {
    return *reinterpret_cast<const __half2*>(&u);
}
__device__ __forceinline__ __half2 ex2_h2(__half2 x) {
    __half2 r;
    asm("ex2.approx.f16x2 %0, %1;"
        : "=r"(*reinterpret_cast<unsigned*>(&r))
        : "r"(*reinterpret_cast<const unsigned*>(&x)));
    return r;
}
__device__ __forceinline__ float ex2f(float x) {
    float r; asm("ex2.approx.f32 %0, %1;" : "=f"(r) : "f"(x)); return r;
}

// ---------- accumulator ----------
struct Acc {
    __half2 a0, a1, a2, a3, hsw;
    float f[8];
    float fsw;
};
__device__ __forceinline__ void flush_all(Acc& A) {
    float2 t;
    t = __half22float2(A.a0);  A.f[0] += t.x; A.f[1] += t.y; A.a0 = __half2(__half2_raw{0,0});
    t = __half22float2(A.a1);  A.f[2] += t.x; A.f[3] += t.y; A.a1 = __half2(__half2_raw{0,0});
    t = __half22float2(A.a2);  A.f[4] += t.x; A.f[5] += t.y; A.a2 = __half2(__half2_raw{0,0});
    t = __half22float2(A.a3);  A.f[6] += t.x; A.f[7] += t.y; A.a3 = __half2(__half2_raw{0,0});
    t = __half22float2(A.hsw); A.fsw  += t.x + t.y;          A.hsw = __half2(__half2_raw{0,0});
}

// ---------- forward pass over positive offsets ----------
template<int I, int JP>
__device__ __forceinline__ void do_pairsF(Acc& A, __half2 I2, const uint4* sQ,
                                          const __half2* sIp, int v0) {
    constexpr int NP = R2.np[I];
    if constexpr (JP < NP) {
        constexpr int dzE  = R2.dzs[I] + 2 * JP;
        constexpr int OFF  = R2.voff[I] + dzE;
        constexpr uu  CP   = R2.cp[I][JP];
        constexpr bool FULL = (JP < NP - 1);

        const int vp = v0 + OFF;
        const __half2 ip  = sIp[vp];
        const __half2 d   = __hsub2(I2, ip);
        const __half2 arg = __hfma2(d, __hneg2(d), hbits(CP));
        const __half2 a2  = ex2_h2(arg);
        A.hsw = __hadd2(A.hsw, a2);
        const uint4 ql = sQ[vp];
        const __half2 aE = __low2half2(a2);
        A.a0 = __hfma2(aE, u2h2(ql.x), A.a0);
        A.a1 = __hfma2(aE, u2h2(ql.y), A.a1);
        A.a2 = __hfma2(aE, u2h2(ql.z), A.a2);
        A.a3 = __hfma2(aE, u2h2(ql.w), A.a3);
        if constexpr (FULL) {
            const uint4 qh = sQ[vp + 1];
            const __half2 aO = __high2half2(a2);
            A.a0 = __hfma2(aO, u2h2(qh.x), A.a0);
            A.a1 = __hfma2(aO, u2h2(qh.y), A.a1);
            A.a2 = __hfma2(aO, u2h2(qh.z), A.a2);
            A.a3 = __hfma2(aO, u2h2(qh.w), A.a3);
        }
        do_pairsF<I, JP + 1>(A, I2, sQ, sIp, v0);
    }
}

template<int I>
__device__ __forceinline__ void do_rowsF(Acc& A, __half2 I2, const uint4* sQ,
                                         const __half2* sIp, int v0) {
    if constexpr (I < 23) {
        do_pairsF<I, 0>(A, I2, sQ, sIp, v0);
        if constexpr (I == 7 || I == 12 || I == 17) flush_all(A);
        do_rowsF<I + 1>(A, I2, sQ, sIp, v0);
    }
}

__global__ __launch_bounds__(512, 2)
void soft_ncuts_main(const float* __restrict__ batch, const float* __restrict__ preds,
                     float* __restrict__ out) {
    extern __shared__ char smem_raw[];
    uint4*          sQ   = (uint4*)smem_raw;
    __half2*        sIp  = (__half2*)(smem_raw + NPAD * 16);
    unsigned short* sIph = (unsigned short*)sIp;

    const int tid = threadIdx.x;
    const int b   = blockIdx.y;
    const int bx  = blockIdx.x;
    const int ox  = (bx >> 3) * 4;
    const int oy  = (bx & 7) * 4;

    const float* batchb = batch + b * 32768;
    const float* predsb = preds + (b * 8) * 32768;

    const float SQ = 0.12011224087864498f;   // sqrt(log2(e))/10

    if (tid == 0) sIph[2 * (NPAD - 1) + 1] = 0;

    // ---- stage padded tile; out-of-volume = EPS ----
    for (int v = tid; v < NPAD; v += 512) {
        int px = v / (TPY * TPZ);
        int r  = v - px * (TPY * TPZ);
        int py = r / TPZ;
        int pz = r - py * TPZ;
        int gx = ox + px - 3, gy = oy + py - 3, gz = pz - 3;
        bool inb = ((unsigned)gx < 32u) && ((unsigned)gy < 32u) && ((unsigned)gz < 32u);
        int g = gx * 1024 + gy * 32 + gz;
        float I = inb ? batchb[g] : EPSV;
        float p[8];
#pragma unroll
        for (int k = 0; k < 8; k++) p[k] = inb ? predsb[k * 32768 + g] : EPSV;
        __half2 h01 = __floats2half2_rn(p[0], p[1]);
        __half2 h23 = __floats2half2_rn(p[2], p[3]);
        __half2 h45 = __floats2half2_rn(p[4], p[5]);
        __half2 h67 = __floats2half2_rn(p[6], p[7]);
        uint4 Q;
        Q.x = *reinterpret_cast<unsigned*>(&h01);
        Q.y = *reinterpret_cast<unsigned*>(&h23);
        Q.z = *reinterpret_cast<unsigned*>(&h45);
        Q.w = *reinterpret_cast<unsigned*>(&h67);
        sQ[v] = Q;
        unsigned short Ih = __half_as_ushort(__float2half_rn(I * SQ));
        sIph[2 * v] = Ih;
        if (v > 0) sIph[2 * v - 1] = Ih;
    }
    __syncthreads();

    const int lz = tid & 31;
    const int wy = (tid >> 5) & 3;
    const int wx = tid >> 7;
    const int v0 = (wx + 3) * (TPY * TPZ) + (wy + 3) * TPZ + (lz + 3);
    const __half2 I2 = __low2half2(sIp[v0]);

    Acc A;
    A.a0 = A.a1 = A.a2 = A.a3 = A.hsw = __half2(__half2_raw{0, 0});
#pragma unroll
    for (int k = 0; k < 8; k++) A.f[k] = 0.f;
    A.fsw = 0.f;

    do_rowsF<0>(A, I2, sQ, sIp, v0);
    flush_all(A);

    // ---- boundary correction from constant table ----
    const int gx = ox + wx, gy = oy + wy, gz = lz;
    const int ix  = gx < 3 ? gx : 3;
    const int iy0 = gy < 3 ? gy : 3;
    const int iy1 = (31 - gy) < 3 ? (31 - gy) : 3;
    const int iz0 = gz < 3 ? gz : 3;
    const int iz1 = (31 - gz) < 3 ? (31 - gz) : 3;
    const float wmf = WTT.w[(((ix * 4 + iy0) * 4 + iy1) * 4 + iz0) * 4 + iz1];

    const float Isf = __half2float(__low2half(I2));
    const float gfac = ex2f(-Isf * Isf);          // exp(-(Ip-eps)^2/100)
    const float vbase = A.fsw + 1.f + gfac * wmf;

    // ---- epilogue: preds from smem (fp16) ----
    const uint4 Q0 = sQ[v0];
    float q[8];
    {
        float2 t;
        t = __half22float2(u2h2(Q0.x)); q[0] = t.x; q[1] = t.y;
        t = __half22float2(u2h2(Q0.y)); q[2] = t.x; q[3] = t.y;
        t = __half22float2(u2h2(Q0.z)); q[4] = t.x; q[5] = t.y;
        t = __half22float2(u2h2(Q0.w)); q[6] = t.x; q[7] = t.y;
    }
    float c[16];
#pragma unroll
    for (int k = 0; k < 8; k++) {
        c[k]     = (2.f * A.f[k] + q[k]) * q[k];   // assocA: 2*cross + diag
        c[8 + k] = q[k] * vbase + A.f[k];          // assocV
    }

    __shared__ float sRed[16];
    if (tid < 16) sRed[tid] = 0.f;
    __syncthreads();
#pragma unroll
    for (int j = 0; j < 16; j++) {
        float val = c[j];
#pragma unroll
        for (int o = 16; o; o >>= 1) val += __shfl_xor_sync(0xffffffffu, val, o);
        if ((tid & 31) == 0) atomicAdd(&sRed[j], val);
    }
    __syncthreads();
    if (tid < 16) gPart[(b * 64 + bx) * 16 + tid] = sRed[tid];
    __syncthreads();

    // ---- fused finalize: last CTA reduces all partials ----
    __shared__ unsigned sLast;
    if (tid == 0) {
        __threadfence();
        unsigned t = atomicAdd(&gCount, 1u);
        sLast = (t == 255u) ? 1u : 0u;
    }
    __syncthreads();
    if (sLast) {
        __shared__ float sAV[64];
        if (tid < 64) sAV[tid] = 0.f;
        __syncthreads();
        if (tid < 256) {
            const int bb = tid >> 6;
            const int jj = (tid >> 2) & 15;
            const int ch = tid & 3;
            float s = 0.f;
#pragma unroll
            for (int t2 = 0; t2 < 16; t2++)
                s += __ldcg(&gPart[(bb * 64 + ch * 16 + t2) * 16 + jj]);
            atomicAdd(&sAV[bb * 16 + jj], s);
        }
        __syncthreads();
        if (tid < 4) {
            float s2 = 0.f;
#pragma unroll
            for (int k = 0; k < 8; k++)
                s2 += sAV[tid * 16 + k] / sAV[tid * 16 + 8 + k];
            out[tid] = 8.f - s2;
        }
        if (tid == 0) gCount = 0u;
    }
}

extern "C" void kernel_launch(void* const* d_in, const int* in_sizes, int n_in,
                              void* d_out, int out_size) {
    const float* batch = (const float*)d_in[0];
    const float* preds = (const float*)d_in[1];
    float* out = (float*)d_out;

    cudaFuncSetAttribute(soft_ncuts_main, cudaFuncAttributeMaxDynamicSharedMemorySize,
                         SMEM_BYTES);

    dim3 grid(64, 4);
    soft_ncuts_main<<<grid, 512, SMEM_BYTES>>>(batch, preds, out);
}